// round 1
// baseline (speedup 1.0000x reference)
#include <cuda_runtime.h>

#define N_SRC 50000
#define N_DST 50000
#define NEDGE 800000
#define IN_DIM 128
#define OUT_DIM 64
#define HEADS 4
#define HC 256              // HEADS * OUT_DIM
#define NEG_SLOPE 0.2f
#define EPS_DEN 1e-16f

// ---------------- scratch (device globals; no allocation allowed) ----------
__device__ float g_hs[(size_t)N_SRC * HC];       // 51.2 MB  projected src feats
__device__ float g_as[N_SRC * HEADS];            // per-node src logits
__device__ float g_ad[N_DST * HEADS];            // per-node dst logits
__device__ float g_vs[IN_DIM * HEADS];           // W_src @ att_src  (folded)
__device__ float g_vd[IN_DIM * HEADS];           // W_dst @ att_dst  (folded)
__device__ float g_denom[N_DST * HEADS];         // softmax denominators
__device__ float g_ep[(size_t)NEDGE * HEADS];    // per-edge exp(logit) 12.8 MB

// ---------------- kernels ---------------------------------------------------

__global__ void k_zero_denom() {
    int i = blockIdx.x * blockDim.x + threadIdx.x;
    if (i < N_DST * HEADS) g_denom[i] = 0.0f;
}

// v_s[k,h] = sum_c W_src[k, h*64+c] * att_src[h,c]   (and same for dst)
__global__ void k_vec(const float* __restrict__ Ws, const float* __restrict__ Wd,
                      const float* __restrict__ att_s, const float* __restrict__ att_d) {
    int t = threadIdx.x;            // 512 threads, 1 block
    int k = t >> 2;
    int h = t & 3;
    float s = 0.0f, d = 0.0f;
#pragma unroll 8
    for (int c = 0; c < OUT_DIM; c++) {
        s += Ws[(size_t)k * HC + h * OUT_DIM + c] * att_s[h * OUT_DIM + c];
        d += Wd[(size_t)k * HC + h * OUT_DIM + c] * att_d[h * OUT_DIM + c];
    }
    g_vs[k * HEADS + h] = s;
    g_vd[k * HEADS + h] = d;
}

// a_s = x_src @ v_s ; a_d = x_dst @ v_d   (N_SRC == N_DST)
__global__ void k_logits(const float* __restrict__ xs, const float* __restrict__ xd) {
    __shared__ float vs[IN_DIM * HEADS];
    __shared__ float vd[IN_DIM * HEADS];
    for (int i = threadIdx.x; i < IN_DIM * HEADS; i += blockDim.x) {
        vs[i] = g_vs[i];
        vd[i] = g_vd[i];
    }
    __syncthreads();
    int n = blockIdx.x * blockDim.x + threadIdx.x;
    if (n >= N_SRC) return;

    float ss[4] = {0.f, 0.f, 0.f, 0.f};
    float dd[4] = {0.f, 0.f, 0.f, 0.f};
    const float4* xr  = reinterpret_cast<const float4*>(xs + (size_t)n * IN_DIM);
    const float4* xdr = reinterpret_cast<const float4*>(xd + (size_t)n * IN_DIM);
#pragma unroll
    for (int k4 = 0; k4 < IN_DIM / 4; k4++) {
        float4 a = xr[k4];
        float4 b = xdr[k4];
        int base = k4 * 4 * HEADS;
#pragma unroll
        for (int h = 0; h < HEADS; h++) {
            ss[h] += a.x * vs[base + 0 * HEADS + h] + a.y * vs[base + 1 * HEADS + h]
                   + a.z * vs[base + 2 * HEADS + h] + a.w * vs[base + 3 * HEADS + h];
            dd[h] += b.x * vd[base + 0 * HEADS + h] + b.y * vd[base + 1 * HEADS + h]
                   + b.z * vd[base + 2 * HEADS + h] + b.w * vd[base + 3 * HEADS + h];
        }
    }
#pragma unroll
    for (int h = 0; h < HEADS; h++) {
        g_as[n * HEADS + h] = ss[h];
        g_ad[n * HEADS + h] = dd[h];
    }
}

// hs = x_src @ W_src  -> g_hs [N_SRC, 256]
#define BM 64
#define BN 64
#define BK 16
__global__ void __launch_bounds__(256) k_gemm(const float* __restrict__ A,
                                              const float* __restrict__ B) {
    __shared__ float As[BK][BM + 4];
    __shared__ float Bs[BK][BN];
    int tid = threadIdx.x;                 // 256 threads
    int tr = tid >> 4;                     // 0..15
    int tc = tid & 15;                     // 0..15
    int rowBase = blockIdx.y * BM;
    int colBase = blockIdx.x * BN;

    int a_r = tid >> 2;                    // 0..63
    int a_c = (tid & 3) * 4;               // 0,4,8,12
    int b_r = tid >> 4;                    // 0..15
    int b_c = (tid & 15) * 4;              // 0..60

    float acc[4][4];
#pragma unroll
    for (int i = 0; i < 4; i++)
#pragma unroll
        for (int j = 0; j < 4; j++) acc[i][j] = 0.0f;

    for (int k0 = 0; k0 < IN_DIM; k0 += BK) {
        float4 av = make_float4(0.f, 0.f, 0.f, 0.f);
        int arow = rowBase + a_r;
        if (arow < N_SRC)
            av = *reinterpret_cast<const float4*>(&A[(size_t)arow * IN_DIM + k0 + a_c]);
        As[a_c + 0][a_r] = av.x;
        As[a_c + 1][a_r] = av.y;
        As[a_c + 2][a_r] = av.z;
        As[a_c + 3][a_r] = av.w;

        float4 bv = *reinterpret_cast<const float4*>(&B[(size_t)(k0 + b_r) * HC + colBase + b_c]);
        *reinterpret_cast<float4*>(&Bs[b_r][b_c]) = bv;
        __syncthreads();

#pragma unroll
        for (int kk = 0; kk < BK; kk++) {
            float4 a4 = *reinterpret_cast<const float4*>(&As[kk][tr * 4]);
            float4 b4 = *reinterpret_cast<const float4*>(&Bs[kk][tc * 4]);
            float a[4] = {a4.x, a4.y, a4.z, a4.w};
            float b[4] = {b4.x, b4.y, b4.z, b4.w};
#pragma unroll
            for (int i = 0; i < 4; i++)
#pragma unroll
                for (int j = 0; j < 4; j++) acc[i][j] += a[i] * b[j];
        }
        __syncthreads();
    }

#pragma unroll
    for (int i = 0; i < 4; i++) {
        int r = rowBase + tr * 4 + i;
        if (r < N_SRC) {
#pragma unroll
            for (int j = 0; j < 4; j++)
                g_hs[(size_t)r * HC + colBase + tc * 4 + j] = acc[i][j];
        }
    }
}

__device__ __forceinline__ float lrelu(float v) {
    return v > 0.0f ? v : NEG_SLOPE * v;
}

// per-edge exp(leaky(a_s[src]+a_d[dst])) ; accumulate softmax denominator
__global__ void k_edge1(const int* __restrict__ src, const int* __restrict__ dst) {
    int e = blockIdx.x * blockDim.x + threadIdx.x;
    if (e >= NEDGE) return;
    int s = src[e], d = dst[e];
    float4 as4 = *reinterpret_cast<const float4*>(&g_as[s * HEADS]);
    float4 ad4 = *reinterpret_cast<const float4*>(&g_ad[d * HEADS]);
    float4 pp;
    pp.x = expf(lrelu(as4.x + ad4.x));
    pp.y = expf(lrelu(as4.y + ad4.y));
    pp.z = expf(lrelu(as4.z + ad4.z));
    pp.w = expf(lrelu(as4.w + ad4.w));
    *reinterpret_cast<float4*>(&g_ep[(size_t)e * HEADS]) = pp;
    atomicAdd(&g_denom[d * HEADS + 0], pp.x);
    atomicAdd(&g_denom[d * HEADS + 1], pp.y);
    atomicAdd(&g_denom[d * HEADS + 2], pp.z);
    atomicAdd(&g_denom[d * HEADS + 3], pp.w);
}

// out[n,c] = bias[c]  (also covers zero-in-degree nodes)
__global__ void k_init_out(float* __restrict__ out, const float* __restrict__ bias) {
    int i = blockIdx.x * blockDim.x + threadIdx.x;
    if (i < N_DST * OUT_DIM) out[i] = bias[i & (OUT_DIM - 1)];
}

// out[dst, c] += 0.25 * sum_h (ep/denom) * hs[src, h*64+c]   (head-mean folded in)
__global__ void k_scatter(const int* __restrict__ src, const int* __restrict__ dst,
                          float* __restrict__ out) {
    int idx = blockIdx.x * blockDim.x + threadIdx.x;
    int e = idx >> 6;          // 64 threads per edge
    int c = idx & 63;
    if (e >= NEDGE) return;
    int s = src[e], d = dst[e];
    float4 p  = *reinterpret_cast<const float4*>(&g_ep[(size_t)e * HEADS]);
    float4 dn = *reinterpret_cast<const float4*>(&g_denom[d * HEADS]);
    float w0 = 0.25f * p.x / (dn.x + EPS_DEN);
    float w1 = 0.25f * p.y / (dn.y + EPS_DEN);
    float w2 = 0.25f * p.z / (dn.z + EPS_DEN);
    float w3 = 0.25f * p.w / (dn.w + EPS_DEN);
    const float* hr = &g_hs[(size_t)s * HC];
    float m = w0 * hr[c] + w1 * hr[64 + c] + w2 * hr[128 + c] + w3 * hr[192 + c];
    atomicAdd(&out[(size_t)d * OUT_DIM + c], m);
}

// ---------------- launch ----------------------------------------------------

extern "C" void kernel_launch(void* const* d_in, const int* in_sizes, int n_in,
                              void* d_out, int out_size) {
    const float* x_src   = (const float*)d_in[0];
    const float* x_dst   = (const float*)d_in[1];
    const int*   ei      = (const int*)d_in[2];   // [2, E] : src row then dst row
    const float* W_src   = (const float*)d_in[3];
    const float* W_dst   = (const float*)d_in[4];
    const float* att_src = (const float*)d_in[5];
    const float* att_dst = (const float*)d_in[6];
    const float* bias    = (const float*)d_in[7];
    float* out = (float*)d_out;

    const int* src = ei;
    const int* dst = ei + NEDGE;

    k_zero_denom<<<(N_DST * HEADS + 255) / 256, 256>>>();
    k_vec<<<1, 512>>>(W_src, W_dst, att_src, att_dst);
    k_logits<<<(N_SRC + 255) / 256, 256>>>(x_src, x_dst);

    dim3 ggrid(HC / BN, (N_SRC + BM - 1) / BM);
    k_gemm<<<ggrid, 256>>>(x_src, W_src);

    k_edge1<<<(NEDGE + 255) / 256, 256>>>(src, dst);
    k_init_out<<<(N_DST * OUT_DIM + 255) / 256, 256>>>(out, bias);
    k_scatter<<<((size_t)NEDGE * 64 + 255) / 256, 256>>>(src, dst, out);
}

// round 2
// speedup vs baseline: 1.2142x; 1.2142x over previous
#include <cuda_runtime.h>

#define N_SRC 50000
#define N_DST 50000
#define NEDGE 800000
#define IN_DIM 128
#define OUT_DIM 64
#define HEADS 4
#define HC 256              // HEADS * OUT_DIM
#define NEG_SLOPE 0.2f
#define EPS_DEN 1e-16f

// ---------------- scratch (device globals; no allocation allowed) ----------
__device__ float g_hs[(size_t)N_SRC * HC];        // 51.2 MB projected src feats
__device__ float g_as[N_SRC * HEADS];             // per-node src logits
__device__ float g_ad[N_DST * HEADS];             // per-node dst logits
__device__ float g_vs[IN_DIM * HEADS];            // W_src @ att_src (folded)
__device__ float g_vd[IN_DIM * HEADS];            // W_dst @ att_dst (folded)
__device__ int   g_deg[N_DST];                    // in-degree histogram
__device__ int   g_off[N_DST];                    // CSR row offsets
__device__ int   g_cur[N_DST];                    // CSR write cursors
__device__ int   g_csr_src[NEDGE];                // CSR-ordered src ids
__device__ float4 g_csr_ep[NEDGE];                // CSR-ordered exp(logits)

// ---------------- kernels ---------------------------------------------------

__global__ void k_zero_deg() {
    int i = blockIdx.x * blockDim.x + threadIdx.x;
    if (i < N_DST) g_deg[i] = 0;
}

// v_s[k,h] = sum_c W_src[k, h*64+c] * att_src[h,c]   (and same for dst)
__global__ void k_vec(const float* __restrict__ Ws, const float* __restrict__ Wd,
                      const float* __restrict__ att_s, const float* __restrict__ att_d) {
    int t = threadIdx.x;            // 512 threads, 1 block
    int k = t >> 2;
    int h = t & 3;
    float s = 0.0f, d = 0.0f;
#pragma unroll 8
    for (int c = 0; c < OUT_DIM; c++) {
        s += Ws[(size_t)k * HC + h * OUT_DIM + c] * att_s[h * OUT_DIM + c];
        d += Wd[(size_t)k * HC + h * OUT_DIM + c] * att_d[h * OUT_DIM + c];
    }
    g_vs[k * HEADS + h] = s;
    g_vd[k * HEADS + h] = d;
}

// a_s = x_src @ v_s ; a_d = x_dst @ v_d   (N_SRC == N_DST)
__global__ void k_logits(const float* __restrict__ xs, const float* __restrict__ xd) {
    __shared__ float vs[IN_DIM * HEADS];
    __shared__ float vd[IN_DIM * HEADS];
    for (int i = threadIdx.x; i < IN_DIM * HEADS; i += blockDim.x) {
        vs[i] = g_vs[i];
        vd[i] = g_vd[i];
    }
    __syncthreads();
    int n = blockIdx.x * blockDim.x + threadIdx.x;
    if (n >= N_SRC) return;

    float ss[4] = {0.f, 0.f, 0.f, 0.f};
    float dd[4] = {0.f, 0.f, 0.f, 0.f};
    const float4* xr  = reinterpret_cast<const float4*>(xs + (size_t)n * IN_DIM);
    const float4* xdr = reinterpret_cast<const float4*>(xd + (size_t)n * IN_DIM);
#pragma unroll
    for (int k4 = 0; k4 < IN_DIM / 4; k4++) {
        float4 a = xr[k4];
        float4 b = xdr[k4];
        int base = k4 * 4 * HEADS;
#pragma unroll
        for (int h = 0; h < HEADS; h++) {
            ss[h] += a.x * vs[base + 0 * HEADS + h] + a.y * vs[base + 1 * HEADS + h]
                   + a.z * vs[base + 2 * HEADS + h] + a.w * vs[base + 3 * HEADS + h];
            dd[h] += b.x * vd[base + 0 * HEADS + h] + b.y * vd[base + 1 * HEADS + h]
                   + b.z * vd[base + 2 * HEADS + h] + b.w * vd[base + 3 * HEADS + h];
        }
    }
#pragma unroll
    for (int h = 0; h < HEADS; h++) {
        g_as[n * HEADS + h] = ss[h];
        g_ad[n * HEADS + h] = dd[h];
    }
}

// hs = x_src @ W_src  -> g_hs [N_SRC, 256].  128x64 tile, 8x4 micro-tile.
#define BM 128
#define BN 64
#define BK 16
__global__ void __launch_bounds__(256) k_gemm(const float* __restrict__ A,
                                              const float* __restrict__ B) {
    __shared__ float As[BK][BM + 4];
    __shared__ float Bs[BK][BN];
    int tid = threadIdx.x;                 // 256 threads
    int tr = tid >> 4;                     // 0..15 -> rows tr*8..tr*8+7
    int tc = tid & 15;                     // 0..15 -> cols tc*4..tc*4+3
    int rowBase = blockIdx.y * BM;
    int colBase = blockIdx.x * BN;

    int a_r = tid >> 1;                    // 0..127
    int a_c = (tid & 1) * 8;               // 0 or 8
    int b_r = tid >> 4;                    // 0..15
    int b_c = (tid & 15) * 4;              // 0..60

    float acc[8][4];
#pragma unroll
    for (int i = 0; i < 8; i++)
#pragma unroll
        for (int j = 0; j < 4; j++) acc[i][j] = 0.0f;

    for (int k0 = 0; k0 < IN_DIM; k0 += BK) {
        float4 av0 = make_float4(0.f, 0.f, 0.f, 0.f);
        float4 av1 = make_float4(0.f, 0.f, 0.f, 0.f);
        int arow = rowBase + a_r;
        if (arow < N_SRC) {
            av0 = *reinterpret_cast<const float4*>(&A[(size_t)arow * IN_DIM + k0 + a_c]);
            av1 = *reinterpret_cast<const float4*>(&A[(size_t)arow * IN_DIM + k0 + a_c + 4]);
        }
        As[a_c + 0][a_r] = av0.x;
        As[a_c + 1][a_r] = av0.y;
        As[a_c + 2][a_r] = av0.z;
        As[a_c + 3][a_r] = av0.w;
        As[a_c + 4][a_r] = av1.x;
        As[a_c + 5][a_r] = av1.y;
        As[a_c + 6][a_r] = av1.z;
        As[a_c + 7][a_r] = av1.w;

        float4 bv = *reinterpret_cast<const float4*>(&B[(size_t)(k0 + b_r) * HC + colBase + b_c]);
        *reinterpret_cast<float4*>(&Bs[b_r][b_c]) = bv;
        __syncthreads();

#pragma unroll
        for (int kk = 0; kk < BK; kk++) {
            float4 a0 = *reinterpret_cast<const float4*>(&As[kk][tr * 8]);
            float4 a1 = *reinterpret_cast<const float4*>(&As[kk][tr * 8 + 4]);
            float4 b4 = *reinterpret_cast<const float4*>(&Bs[kk][tc * 4]);
            float a[8] = {a0.x, a0.y, a0.z, a0.w, a1.x, a1.y, a1.z, a1.w};
            float b[4] = {b4.x, b4.y, b4.z, b4.w};
#pragma unroll
            for (int i = 0; i < 8; i++)
#pragma unroll
                for (int j = 0; j < 4; j++) acc[i][j] += a[i] * b[j];
        }
        __syncthreads();
    }

#pragma unroll
    for (int i = 0; i < 8; i++) {
        int r = rowBase + tr * 8 + i;
        if (r < N_SRC) {
            float4 v = make_float4(acc[i][0], acc[i][1], acc[i][2], acc[i][3]);
            *reinterpret_cast<float4*>(&g_hs[(size_t)r * HC + colBase + tc * 4]) = v;
        }
    }
}

// in-degree histogram
__global__ void k_hist(const int* __restrict__ dst) {
    int e = blockIdx.x * blockDim.x + threadIdx.x;
    if (e < NEDGE) atomicAdd(&g_deg[dst[e]], 1);
}

// exclusive scan of g_deg -> g_off, g_cur.  Single block of 1024 threads.
__global__ void __launch_bounds__(1024) k_scan() {
    __shared__ int sums[1024];
    const int CH = (N_DST + 1023) / 1024;   // 49
    int t = threadIdx.x;
    int beg = t * CH;
    int end = beg + CH; if (end > N_DST) end = N_DST;
    int s = 0;
    for (int i = beg; i < end; i++) s += g_deg[i];
    sums[t] = s;
    __syncthreads();
    for (int off = 1; off < 1024; off <<= 1) {
        int v = (t >= off) ? sums[t - off] : 0;
        __syncthreads();
        sums[t] += v;
        __syncthreads();
    }
    int run = (t == 0) ? 0 : sums[t - 1];
    for (int i = beg; i < end; i++) {
        g_off[i] = run;
        g_cur[i] = run;
        run += g_deg[i];
    }
}

__device__ __forceinline__ float lrelu(float v) {
    return v > 0.0f ? v : NEG_SLOPE * v;
}

// per-edge exp(leaky(a_s[src]+a_d[dst])), bucketed into CSR order
__global__ void k_edge(const int* __restrict__ src, const int* __restrict__ dst) {
    int e = blockIdx.x * blockDim.x + threadIdx.x;
    if (e >= NEDGE) return;
    int s = src[e], d = dst[e];
    float4 as4 = *reinterpret_cast<const float4*>(&g_as[s * HEADS]);
    float4 ad4 = *reinterpret_cast<const float4*>(&g_ad[d * HEADS]);
    float4 pp;
    pp.x = expf(lrelu(as4.x + ad4.x));
    pp.y = expf(lrelu(as4.y + ad4.y));
    pp.z = expf(lrelu(as4.z + ad4.z));
    pp.w = expf(lrelu(as4.w + ad4.w));
    int pos = atomicAdd(&g_cur[d], 1);
    g_csr_src[pos] = s;
    g_csr_ep[pos] = pp;
}

// gather: 64 threads per dst node (4 nodes / 256-thread block); no atomics.
__global__ void __launch_bounds__(256) k_gather(const float* __restrict__ bias,
                                                float* __restrict__ out) {
    int node = blockIdx.x * 4 + (threadIdx.x >> 6);
    int c = threadIdx.x & 63;
    if (node >= N_DST) return;
    int beg = g_off[node];
    int n = g_deg[node];
    int end = beg + n;

    float d0 = 0.f, d1 = 0.f, d2 = 0.f, d3 = 0.f;
    for (int i = beg; i < end; i++) {
        float4 p = g_csr_ep[i];      // broadcast across the 64-thread group
        d0 += p.x; d1 += p.y; d2 += p.z; d3 += p.w;
    }
    float r0 = 0.25f / (d0 + EPS_DEN);
    float r1 = 0.25f / (d1 + EPS_DEN);
    float r2 = 0.25f / (d2 + EPS_DEN);
    float r3 = 0.25f / (d3 + EPS_DEN);

    float acc = 0.f;
    for (int i = beg; i < end; i++) {
        int s = g_csr_src[i];
        float4 p = g_csr_ep[i];
        const float* hr = &g_hs[(size_t)s * HC];
        acc += (p.x * r0) * hr[c] + (p.y * r1) * hr[64 + c]
             + (p.z * r2) * hr[128 + c] + (p.w * r3) * hr[192 + c];
    }
    out[(size_t)node * OUT_DIM + c] = acc + bias[c];
}

// ---------------- launch ----------------------------------------------------

extern "C" void kernel_launch(void* const* d_in, const int* in_sizes, int n_in,
                              void* d_out, int out_size) {
    const float* x_src   = (const float*)d_in[0];
    const float* x_dst   = (const float*)d_in[1];
    const int*   ei      = (const int*)d_in[2];   // [2, E] : src row then dst row
    const float* W_src   = (const float*)d_in[3];
    const float* W_dst   = (const float*)d_in[4];
    const float* att_src = (const float*)d_in[5];
    const float* att_dst = (const float*)d_in[6];
    const float* bias    = (const float*)d_in[7];
    float* out = (float*)d_out;

    const int* src = ei;
    const int* dst = ei + NEDGE;

    k_zero_deg<<<(N_DST + 255) / 256, 256>>>();
    k_vec<<<1, 512>>>(W_src, W_dst, att_src, att_dst);
    k_logits<<<(N_SRC + 255) / 256, 256>>>(x_src, x_dst);

    dim3 ggrid(HC / BN, (N_SRC + BM - 1) / BM);
    k_gemm<<<ggrid, 256>>>(x_src, W_src);

    k_hist<<<(NEDGE + 255) / 256, 256>>>(dst);
    k_scan<<<1, 1024>>>();
    k_edge<<<(NEDGE + 255) / 256, 256>>>(src, dst);
    k_gather<<<(N_DST + 3) / 4, 256>>>(bias, out);
}

// round 3
// speedup vs baseline: 1.3938x; 1.1479x over previous
#include <cuda_runtime.h>
#include <cuda_fp16.h>

#define N_SRC 50000
#define N_DST 50000
#define NEDGE 800000
#define IN_DIM 128
#define OUT_DIM 64
#define HEADS 4
#define HC 256              // HEADS * OUT_DIM
#define NEG_SLOPE 0.2f
#define EPS_DEN 1e-16f

// ---------------- scratch (device globals; no allocation allowed) ----------
__device__ __half g_hsh[(size_t)N_SRC * HC];      // 25.6 MB projected src feats (fp16)
__device__ float g_as[N_SRC * HEADS];             // per-node src logits
__device__ float g_ad[N_DST * HEADS];             // per-node dst logits
__device__ float g_vs[IN_DIM * HEADS];            // W_src @ att_src (folded)
__device__ float g_vd[IN_DIM * HEADS];            // W_dst @ att_dst (folded)
__device__ int   g_deg[N_DST];                    // in-degree histogram
__device__ int   g_off[N_DST];                    // CSR row offsets
__device__ int   g_cur[N_DST];                    // CSR write cursors
__device__ int   g_csr_src[NEDGE];                // CSR-ordered src ids
__device__ float4 g_csr_ep[NEDGE];                // CSR-ordered exp(logits)

// ---------------- f32x2 helpers (sm_100+) -----------------------------------
__device__ __forceinline__ unsigned long long pack2(float x, float y) {
    unsigned long long r;
    asm("mov.b64 %0, {%1, %2};" : "=l"(r) : "f"(x), "f"(y));
    return r;
}
__device__ __forceinline__ float2 unpack2(unsigned long long v) {
    float2 r;
    asm("mov.b64 {%0, %1}, %2;" : "=f"(r.x), "=f"(r.y) : "l"(v));
    return r;
}
__device__ __forceinline__ void ffma2(unsigned long long& d,
                                      unsigned long long a, unsigned long long b) {
    asm("fma.rn.f32x2 %0, %1, %2, %0;" : "+l"(d) : "l"(a), "l"(b));
}

// ---------------- kernels ---------------------------------------------------

__global__ void k_zero_deg() {
    int i = blockIdx.x * blockDim.x + threadIdx.x;
    if (i < N_DST) g_deg[i] = 0;
}

// v_s[k,h] = sum_c W_src[k, h*64+c] * att_src[h,c]   (and same for dst)
__global__ void k_vec(const float* __restrict__ Ws, const float* __restrict__ Wd,
                      const float* __restrict__ att_s, const float* __restrict__ att_d) {
    int t = threadIdx.x;            // 512 threads, 1 block
    int k = t >> 2;
    int h = t & 3;
    float s = 0.0f, d = 0.0f;
#pragma unroll 8
    for (int c = 0; c < OUT_DIM; c++) {
        s += Ws[(size_t)k * HC + h * OUT_DIM + c] * att_s[h * OUT_DIM + c];
        d += Wd[(size_t)k * HC + h * OUT_DIM + c] * att_d[h * OUT_DIM + c];
    }
    g_vs[k * HEADS + h] = s;
    g_vd[k * HEADS + h] = d;
}

// a_s = x_src @ v_s ; a_d = x_dst @ v_d   (N_SRC == N_DST)
__global__ void k_logits(const float* __restrict__ xs, const float* __restrict__ xd) {
    __shared__ float vs[IN_DIM * HEADS];
    __shared__ float vd[IN_DIM * HEADS];
    for (int i = threadIdx.x; i < IN_DIM * HEADS; i += blockDim.x) {
        vs[i] = g_vs[i];
        vd[i] = g_vd[i];
    }
    __syncthreads();
    int n = blockIdx.x * blockDim.x + threadIdx.x;
    if (n >= N_SRC) return;

    float ss[4] = {0.f, 0.f, 0.f, 0.f};
    float dd[4] = {0.f, 0.f, 0.f, 0.f};
    const float4* xr  = reinterpret_cast<const float4*>(xs + (size_t)n * IN_DIM);
    const float4* xdr = reinterpret_cast<const float4*>(xd + (size_t)n * IN_DIM);
#pragma unroll
    for (int k4 = 0; k4 < IN_DIM / 4; k4++) {
        float4 a = xr[k4];
        float4 b = xdr[k4];
        int base = k4 * 4 * HEADS;
#pragma unroll
        for (int h = 0; h < HEADS; h++) {
            ss[h] += a.x * vs[base + 0 * HEADS + h] + a.y * vs[base + 1 * HEADS + h]
                   + a.z * vs[base + 2 * HEADS + h] + a.w * vs[base + 3 * HEADS + h];
            dd[h] += b.x * vd[base + 0 * HEADS + h] + b.y * vd[base + 1 * HEADS + h]
                   + b.z * vd[base + 2 * HEADS + h] + b.w * vd[base + 3 * HEADS + h];
        }
    }
#pragma unroll
    for (int h = 0; h < HEADS; h++) {
        g_as[n * HEADS + h] = ss[h];
        g_ad[n * HEADS + h] = dd[h];
    }
}

// hs = x_src @ W_src -> g_hsh [N_SRC, 256] fp16.
// 128x64 tile, 8x4 micro-tile held as 4 row-pairs of f32x2 accumulators.
#define BM 128
#define BN 64
#define BK 16
__global__ void __launch_bounds__(256) k_gemm(const float* __restrict__ A,
                                              const float* __restrict__ B) {
    __shared__ float As[BK][BM + 4];
    __shared__ float Bs[BK][BN];
    int tid = threadIdx.x;                 // 256 threads
    int tr = tid >> 4;                     // 0..15 -> rows tr*8..tr*8+7
    int tc = tid & 15;                     // 0..15 -> cols tc*4..tc*4+3
    int rowBase = blockIdx.y * BM;
    int colBase = blockIdx.x * BN;

    int a_r = tid >> 1;                    // 0..127
    int a_c = (tid & 1) * 8;               // 0 or 8
    int b_r = tid >> 4;                    // 0..15
    int b_c = (tid & 15) * 4;              // 0..60

    // acc2[ip][j]: packed rows (tr*8+2ip, tr*8+2ip+1), column j
    unsigned long long acc2[4][4];
#pragma unroll
    for (int i = 0; i < 4; i++)
#pragma unroll
        for (int j = 0; j < 4; j++) acc2[i][j] = 0ULL;

    for (int k0 = 0; k0 < IN_DIM; k0 += BK) {
        float4 av0 = make_float4(0.f, 0.f, 0.f, 0.f);
        float4 av1 = make_float4(0.f, 0.f, 0.f, 0.f);
        int arow = rowBase + a_r;
        if (arow < N_SRC) {
            av0 = *reinterpret_cast<const float4*>(&A[(size_t)arow * IN_DIM + k0 + a_c]);
            av1 = *reinterpret_cast<const float4*>(&A[(size_t)arow * IN_DIM + k0 + a_c + 4]);
        }
        As[a_c + 0][a_r] = av0.x;
        As[a_c + 1][a_r] = av0.y;
        As[a_c + 2][a_r] = av0.z;
        As[a_c + 3][a_r] = av0.w;
        As[a_c + 4][a_r] = av1.x;
        As[a_c + 5][a_r] = av1.y;
        As[a_c + 6][a_r] = av1.z;
        As[a_c + 7][a_r] = av1.w;

        float4 bv = *reinterpret_cast<const float4*>(&B[(size_t)(k0 + b_r) * HC + colBase + b_c]);
        *reinterpret_cast<float4*>(&Bs[b_r][b_c]) = bv;
        __syncthreads();

#pragma unroll
        for (int kk = 0; kk < BK; kk++) {
            float4 a0 = *reinterpret_cast<const float4*>(&As[kk][tr * 8]);
            float4 a1 = *reinterpret_cast<const float4*>(&As[kk][tr * 8 + 4]);
            float4 b4 = *reinterpret_cast<const float4*>(&Bs[kk][tc * 4]);
            unsigned long long ap[4];
            ap[0] = pack2(a0.x, a0.y);
            ap[1] = pack2(a0.z, a0.w);
            ap[2] = pack2(a1.x, a1.y);
            ap[3] = pack2(a1.z, a1.w);
            unsigned long long bd[4];
            bd[0] = pack2(b4.x, b4.x);
            bd[1] = pack2(b4.y, b4.y);
            bd[2] = pack2(b4.z, b4.z);
            bd[3] = pack2(b4.w, b4.w);
#pragma unroll
            for (int ip = 0; ip < 4; ip++)
#pragma unroll
                for (int j = 0; j < 4; j++) ffma2(acc2[ip][j], ap[ip], bd[j]);
        }
        __syncthreads();
    }

#pragma unroll
    for (int ip = 0; ip < 4; ip++) {
        float2 u0 = unpack2(acc2[ip][0]);
        float2 u1 = unpack2(acc2[ip][1]);
        float2 u2 = unpack2(acc2[ip][2]);
        float2 u3 = unpack2(acc2[ip][3]);
        int r0 = rowBase + tr * 8 + 2 * ip;
        if (r0 < N_SRC) {
            __half2 h01 = __floats2half2_rn(u0.x, u1.x);
            __half2 h23 = __floats2half2_rn(u2.x, u3.x);
            uint2 st;
            st.x = *reinterpret_cast<unsigned*>(&h01);
            st.y = *reinterpret_cast<unsigned*>(&h23);
            *reinterpret_cast<uint2*>(&g_hsh[(size_t)r0 * HC + colBase + tc * 4]) = st;
        }
        if (r0 + 1 < N_SRC) {
            __half2 h01 = __floats2half2_rn(u0.y, u1.y);
            __half2 h23 = __floats2half2_rn(u2.y, u3.y);
            uint2 st;
            st.x = *reinterpret_cast<unsigned*>(&h01);
            st.y = *reinterpret_cast<unsigned*>(&h23);
            *reinterpret_cast<uint2*>(&g_hsh[(size_t)(r0 + 1) * HC + colBase + tc * 4]) = st;
        }
    }
}

// in-degree histogram
__global__ void k_hist(const int* __restrict__ dst) {
    int e = blockIdx.x * blockDim.x + threadIdx.x;
    if (e < NEDGE) atomicAdd(&g_deg[dst[e]], 1);
}

// exclusive scan of g_deg -> g_off, g_cur.  Single block of 1024 threads.
__global__ void __launch_bounds__(1024) k_scan() {
    __shared__ int sums[1024];
    const int CH = (N_DST + 1023) / 1024;   // 49
    int t = threadIdx.x;
    int beg = t * CH;
    int end = beg + CH; if (end > N_DST) end = N_DST;
    int s = 0;
    for (int i = beg; i < end; i++) s += g_deg[i];
    sums[t] = s;
    __syncthreads();
    for (int off = 1; off < 1024; off <<= 1) {
        int v = (t >= off) ? sums[t - off] : 0;
        __syncthreads();
        sums[t] += v;
        __syncthreads();
    }
    int run = (t == 0) ? 0 : sums[t - 1];
    for (int i = beg; i < end; i++) {
        g_off[i] = run;
        g_cur[i] = run;
        run += g_deg[i];
    }
}

__device__ __forceinline__ float lrelu(float v) {
    return v > 0.0f ? v : NEG_SLOPE * v;
}

// per-edge exp(leaky(a_s[src]+a_d[dst])), bucketed into CSR order
__global__ void k_edge(const int* __restrict__ src, const int* __restrict__ dst) {
    int e = blockIdx.x * blockDim.x + threadIdx.x;
    if (e >= NEDGE) return;
    int s = src[e], d = dst[e];
    float4 as4 = *reinterpret_cast<const float4*>(&g_as[s * HEADS]);
    float4 ad4 = *reinterpret_cast<const float4*>(&g_ad[d * HEADS]);
    float4 pp;
    pp.x = expf(lrelu(as4.x + ad4.x));
    pp.y = expf(lrelu(as4.y + ad4.y));
    pp.z = expf(lrelu(as4.z + ad4.z));
    pp.w = expf(lrelu(as4.w + ad4.w));
    int pos = atomicAdd(&g_cur[d], 1);
    g_csr_src[pos] = s;
    g_csr_ep[pos] = pp;
}

// gather: 1 warp per dst node, each thread owns 2 channels (c = 2*lane, 2*lane+1).
__global__ void __launch_bounds__(256) k_gather(const float* __restrict__ bias,
                                                float* __restrict__ out) {
    int node = blockIdx.x * 8 + (threadIdx.x >> 5);
    int c2 = threadIdx.x & 31;          // half2 index within a head
    if (node >= N_DST) return;
    int beg = g_off[node];
    int end = beg + g_deg[node];

    float d0 = 0.f, d1 = 0.f, d2 = 0.f, d3 = 0.f;
    for (int i = beg; i < end; i++) {
        float4 p = g_csr_ep[i];          // broadcast within warp
        d0 += p.x; d1 += p.y; d2 += p.z; d3 += p.w;
    }
    float r0 = 0.25f / (d0 + EPS_DEN);
    float r1 = 0.25f / (d1 + EPS_DEN);
    float r2 = 0.25f / (d2 + EPS_DEN);
    float r3 = 0.25f / (d3 + EPS_DEN);

    float ax = 0.f, ay = 0.f;
    for (int i = beg; i < end; i++) {
        int s = g_csr_src[i];
        float4 p = g_csr_ep[i];
        const __half2* hr = reinterpret_cast<const __half2*>(&g_hsh[(size_t)s * HC]);
        float2 f0 = __half22float2(hr[c2]);
        float2 f1 = __half22float2(hr[32 + c2]);
        float2 f2 = __half22float2(hr[64 + c2]);
        float2 f3 = __half22float2(hr[96 + c2]);
        float w0 = p.x * r0, w1 = p.y * r1, w2 = p.z * r2, w3 = p.w * r3;
        ax += w0 * f0.x + w1 * f1.x + w2 * f2.x + w3 * f3.x;
        ay += w0 * f0.y + w1 * f1.y + w2 * f2.y + w3 * f3.y;
    }
    float2 res;
    res.x = ax + bias[c2 * 2];
    res.y = ay + bias[c2 * 2 + 1];
    *reinterpret_cast<float2*>(&out[(size_t)node * OUT_DIM + c2 * 2]) = res;
}

// ---------------- launch ----------------------------------------------------

extern "C" void kernel_launch(void* const* d_in, const int* in_sizes, int n_in,
                              void* d_out, int out_size) {
    const float* x_src   = (const float*)d_in[0];
    const float* x_dst   = (const float*)d_in[1];
    const int*   ei      = (const int*)d_in[2];   // [2, E] : src row then dst row
    const float* W_src   = (const float*)d_in[3];
    const float* W_dst   = (const float*)d_in[4];
    const float* att_src = (const float*)d_in[5];
    const float* att_dst = (const float*)d_in[6];
    const float* bias    = (const float*)d_in[7];
    float* out = (float*)d_out;

    const int* src = ei;
    const int* dst = ei + NEDGE;

    k_zero_deg<<<(N_DST + 255) / 256, 256>>>();
    k_vec<<<1, 512>>>(W_src, W_dst, att_src, att_dst);
    k_logits<<<(N_SRC + 255) / 256, 256>>>(x_src, x_dst);

    dim3 ggrid(HC / BN, (N_SRC + BM - 1) / BM);
    k_gemm<<<ggrid, 256>>>(x_src, W_src);

    k_hist<<<(NEDGE + 255) / 256, 256>>>(dst);
    k_scan<<<1, 1024>>>();
    k_edge<<<(NEDGE + 255) / 256, 256>>>(src, dst);
    k_gather<<<(N_DST + 7) / 8, 256>>>(bias, out);
}

// round 5
// speedup vs baseline: 1.6286x; 1.1685x over previous
#include <cuda_runtime.h>
#include <cuda_fp16.h>
#include <cstdint>

#define N_SRC 50000
#define N_DST 50000
#define NEDGE 800000
#define IN_DIM 128
#define OUT_DIM 64
#define HEADS 4
#define HC 256              // HEADS * OUT_DIM
#define NEG_SLOPE 0.2f
#define EPS_DEN 1e-16f

#define M_TILES ((N_SRC + 127) / 128)   // 391

// ---------------- scratch (device globals; no allocation allowed) ----------
__device__ __half g_hsh[(size_t)N_SRC * HC];      // 25.6 MB projected src feats (fp16)
__device__ __half g_wt[256 * 128];                // W^T fp16 [n][k] row-major (64KB)
__device__ float g_as[N_SRC * HEADS];             // per-node src logits
__device__ float g_ad[N_DST * HEADS];             // per-node dst logits
__device__ float g_vs[IN_DIM * HEADS];            // W_src @ att_src (folded)
__device__ float g_vd[IN_DIM * HEADS];            // W_dst @ att_dst (folded)
__device__ int   g_deg[N_DST];                    // in-degree histogram
__device__ int   g_off[N_DST];                    // CSR row offsets
__device__ int   g_cur[N_DST];                    // CSR write cursors
__device__ int   g_csr_src[NEDGE];                // CSR-ordered src ids
__device__ float4 g_csr_ep[NEDGE];                // CSR-ordered exp(logits)

// ---------------- mma/ldmatrix helpers (family-portable, sm_80+) -----------
__device__ __forceinline__ void ldsm_x4(uint32_t& r0, uint32_t& r1, uint32_t& r2,
                                        uint32_t& r3, uint32_t addr) {
    asm volatile("ldmatrix.sync.aligned.m8n8.x4.shared.b16 {%0,%1,%2,%3}, [%4];"
                 : "=r"(r0), "=r"(r1), "=r"(r2), "=r"(r3) : "r"(addr));
}
__device__ __forceinline__ void mma16816(float& d0, float& d1, float& d2, float& d3,
                                         uint32_t a0, uint32_t a1, uint32_t a2, uint32_t a3,
                                         uint32_t b0, uint32_t b1) {
    asm volatile(
        "mma.sync.aligned.m16n8k16.row.col.f32.f16.f16.f32 "
        "{%0,%1,%2,%3}, {%4,%5,%6,%7}, {%8,%9}, {%0,%1,%2,%3};"
        : "+f"(d0), "+f"(d1), "+f"(d2), "+f"(d3)
        : "r"(a0), "r"(a1), "r"(a2), "r"(a3), "r"(b0), "r"(b1));
}

// ---------------- kernels ---------------------------------------------------

__global__ void k_zero_deg() {
    int i = blockIdx.x * blockDim.x + threadIdx.x;
    if (i < N_DST) g_deg[i] = 0;
}

// transpose + fp16-convert W_src -> g_wt [n=256][k=128] row-major
__global__ void k_wt(const float* __restrict__ W) {
    int t = blockIdx.x * blockDim.x + threadIdx.x;   // 0..16383 (one half2 each)
    int n = t & 255;
    int k2 = t >> 8;                                 // half2 index 0..63
    float w0 = W[(size_t)(2 * k2) * HC + n];
    float w1 = W[(size_t)(2 * k2 + 1) * HC + n];
    __half2 h = __floats2half2_rn(w0, w1);
    *reinterpret_cast<__half2*>(&g_wt[n * 128 + 2 * k2]) = h;
}

// v_s[k,h] = sum_c W_src[k, h*64+c] * att_src[h,c]   (and same for dst)
__global__ void k_vec(const float* __restrict__ Ws, const float* __restrict__ Wd,
                      const float* __restrict__ att_s, const float* __restrict__ att_d) {
    int t = threadIdx.x;            // 512 threads, 1 block
    int k = t >> 2;
    int h = t & 3;
    float s = 0.0f, d = 0.0f;
#pragma unroll 8
    for (int c = 0; c < OUT_DIM; c++) {
        s += Ws[(size_t)k * HC + h * OUT_DIM + c] * att_s[h * OUT_DIM + c];
        d += Wd[(size_t)k * HC + h * OUT_DIM + c] * att_d[h * OUT_DIM + c];
    }
    g_vs[k * HEADS + h] = s;
    g_vd[k * HEADS + h] = d;
}

// a_s = x_src @ v_s ; a_d = x_dst @ v_d   (N_SRC == N_DST)
__global__ void k_logits(const float* __restrict__ xs, const float* __restrict__ xd) {
    __shared__ float vs[IN_DIM * HEADS];
    __shared__ float vd[IN_DIM * HEADS];
    for (int i = threadIdx.x; i < IN_DIM * HEADS; i += blockDim.x) {
        vs[i] = g_vs[i];
        vd[i] = g_vd[i];
    }
    __syncthreads();
    int n = blockIdx.x * blockDim.x + threadIdx.x;
    if (n >= N_SRC) return;

    float ss[4] = {0.f, 0.f, 0.f, 0.f};
    float dd[4] = {0.f, 0.f, 0.f, 0.f};
    const float4* xr  = reinterpret_cast<const float4*>(xs + (size_t)n * IN_DIM);
    const float4* xdr = reinterpret_cast<const float4*>(xd + (size_t)n * IN_DIM);
#pragma unroll
    for (int k4 = 0; k4 < IN_DIM / 4; k4++) {
        float4 a = xr[k4];
        float4 b = xdr[k4];
        int base = k4 * 4 * HEADS;
#pragma unroll
        for (int h = 0; h < HEADS; h++) {
            ss[h] += a.x * vs[base + 0 * HEADS + h] + a.y * vs[base + 1 * HEADS + h]
                   + a.z * vs[base + 2 * HEADS + h] + a.w * vs[base + 3 * HEADS + h];
            dd[h] += b.x * vd[base + 0 * HEADS + h] + b.y * vd[base + 1 * HEADS + h]
                   + b.z * vd[base + 2 * HEADS + h] + b.w * vd[base + 3 * HEADS + h];
        }
    }
#pragma unroll
    for (int h = 0; h < HEADS; h++) {
        g_as[n * HEADS + h] = ss[h];
        g_ad[n * HEADS + h] = dd[h];
    }
}

// hs = x_src @ W_src via HMMA (fp16 in, f32 accum) -> g_hsh [N_SRC, 256] fp16
// CTA tile M=128 N=256 K=128; 16 warps (4x4), warp tile 32x64.
// SMEM rows padded to 272B (17*16) -> ldmatrix conflict-free.
#define AS_STRIDE 272
#define AS_BYTES (128 * AS_STRIDE)       // 34816
#define BS_BYTES (256 * AS_STRIDE)       // 69632
#define SM_TOTAL (AS_BYTES + BS_BYTES)   // 104448

__global__ void __launch_bounds__(512) k_gemm_mma(const float* __restrict__ A) {
    extern __shared__ char smem[];
    char* As = smem;
    char* Bs = smem + AS_BYTES;
    int tid = threadIdx.x;
    int lane = tid & 31;
    int warp = tid >> 5;
    int rowBase = blockIdx.x * 128;

    // load + convert A tile: 128 rows x 128 f16 (rows padded to 272B)
    for (int i = tid; i < 128 * 32; i += 512) {
        int r = i >> 5;
        int c4 = i & 31;                 // float4 index
        int grow = rowBase + r;
        float4 v = make_float4(0.f, 0.f, 0.f, 0.f);
        if (grow < N_SRC)
            v = *reinterpret_cast<const float4*>(&A[(size_t)grow * IN_DIM + c4 * 4]);
        __half2 h0 = __floats2half2_rn(v.x, v.y);
        __half2 h1 = __floats2half2_rn(v.z, v.w);
        uint2 st;
        st.x = *reinterpret_cast<uint32_t*>(&h0);
        st.y = *reinterpret_cast<uint32_t*>(&h1);
        *reinterpret_cast<uint2*>(As + r * AS_STRIDE + c4 * 8) = st;
    }
    // copy W^T image: 256 rows x 256B
    for (int i = tid; i < 256 * 16; i += 512) {
        int r = i >> 4;
        int c = i & 15;                  // uint4 index
        uint4 v = *reinterpret_cast<const uint4*>(&g_wt[r * 128 + c * 8]);
        *reinterpret_cast<uint4*>(Bs + r * AS_STRIDE + c * 16) = v;
    }
    __syncthreads();

    int wm = warp >> 2;                  // 0..3 -> m0 = wm*32
    int wn = warp & 3;                   // 0..3 -> n0 = wn*64
    int m0 = wm * 32;
    int n0 = wn * 64;

    float acc[2][8][4];
#pragma unroll
    for (int mi = 0; mi < 2; mi++)
#pragma unroll
        for (int ni = 0; ni < 8; ni++)
#pragma unroll
            for (int q = 0; q < 4; q++) acc[mi][ni][q] = 0.f;

    uint32_t asb = (uint32_t)__cvta_generic_to_shared(As);
    uint32_t bsb = (uint32_t)__cvta_generic_to_shared(Bs);

#pragma unroll
    for (int ks = 0; ks < 8; ks++) {
        int kb = ks * 32;                // byte offset of k-chunk (16 f16)

        uint32_t a[2][4];
#pragma unroll
        for (int mi = 0; mi < 2; mi++) {
            uint32_t addr = asb + (m0 + mi * 16 + (lane & 15)) * AS_STRIDE
                          + kb + (lane >> 4) * 16;
            ldsm_x4(a[mi][0], a[mi][1], a[mi][2], a[mi][3], addr);
        }
        // B: each x4 covers two n-tiles (16 n rows)
        uint32_t b[8][2];
#pragma unroll
        for (int np = 0; np < 4; np++) {
            int q = lane >> 3;           // 0..3
            int row = n0 + np * 16 + (q >> 1) * 8 + (lane & 7);
            uint32_t addr = bsb + row * AS_STRIDE + kb + (q & 1) * 16;
            ldsm_x4(b[np * 2][0], b[np * 2][1], b[np * 2 + 1][0], b[np * 2 + 1][1], addr);
        }
#pragma unroll
        for (int mi = 0; mi < 2; mi++)
#pragma unroll
            for (int ni = 0; ni < 8; ni++)
                mma16816(acc[mi][ni][0], acc[mi][ni][1], acc[mi][ni][2], acc[mi][ni][3],
                         a[mi][0], a[mi][1], a[mi][2], a[mi][3],
                         b[ni][0], b[ni][1]);
    }

    // epilogue: c-frag (d0,d1)@(row=lane/4, col=2*(lane%4)), (d2,d3)@row+8
#pragma unroll
    for (int mi = 0; mi < 2; mi++) {
        int r0 = rowBase + m0 + mi * 16 + (lane >> 2);
        int r1 = r0 + 8;
#pragma unroll
        for (int ni = 0; ni < 8; ni++) {
            int col = n0 + ni * 8 + 2 * (lane & 3);
            if (r0 < N_SRC) {
                __half2 h = __floats2half2_rn(acc[mi][ni][0], acc[mi][ni][1]);
                *reinterpret_cast<__half2*>(&g_hsh[(size_t)r0 * HC + col]) = h;
            }
            if (r1 < N_SRC) {
                __half2 h = __floats2half2_rn(acc[mi][ni][2], acc[mi][ni][3]);
                *reinterpret_cast<__half2*>(&g_hsh[(size_t)r1 * HC + col]) = h;
            }
        }
    }
}

// in-degree histogram
__global__ void k_hist(const int* __restrict__ dst) {
    int e = blockIdx.x * blockDim.x + threadIdx.x;
    if (e < NEDGE) atomicAdd(&g_deg[dst[e]], 1);
}

// exclusive scan of g_deg -> g_off, g_cur.  Single block of 1024 threads.
__global__ void __launch_bounds__(1024) k_scan() {
    __shared__ int sums[1024];
    const int CH = (N_DST + 1023) / 1024;   // 49
    int t = threadIdx.x;
    int beg = t * CH;
    int end = beg + CH; if (end > N_DST) end = N_DST;
    int s = 0;
    for (int i = beg; i < end; i++) s += g_deg[i];
    sums[t] = s;
    __syncthreads();
    for (int off = 1; off < 1024; off <<= 1) {
        int v = (t >= off) ? sums[t - off] : 0;
        __syncthreads();
        sums[t] += v;
        __syncthreads();
    }
    int run = (t == 0) ? 0 : sums[t - 1];
    for (int i = beg; i < end; i++) {
        g_off[i] = run;
        g_cur[i] = run;
        run += g_deg[i];
    }
}

__device__ __forceinline__ float lrelu(float v) {
    return v > 0.0f ? v : NEG_SLOPE * v;
}

// per-edge exp(leaky(a_s[src]+a_d[dst])), bucketed into CSR order
__global__ void k_edge(const int* __restrict__ src, const int* __restrict__ dst) {
    int e = blockIdx.x * blockDim.x + threadIdx.x;
    if (e >= NEDGE) return;
    int s = src[e], d = dst[e];
    float4 as4 = *reinterpret_cast<const float4*>(&g_as[s * HEADS]);
    float4 ad4 = *reinterpret_cast<const float4*>(&g_ad[d * HEADS]);
    float4 pp;
    pp.x = expf(lrelu(as4.x + ad4.x));
    pp.y = expf(lrelu(as4.y + ad4.y));
    pp.z = expf(lrelu(as4.z + ad4.z));
    pp.w = expf(lrelu(as4.w + ad4.w));
    int pos = atomicAdd(&g_cur[d], 1);
    g_csr_src[pos] = s;
    g_csr_ep[pos] = pp;
}

// gather: 1 warp per dst node, each thread owns 2 channels.
__global__ void __launch_bounds__(256) k_gather(const float* __restrict__ bias,
                                                float* __restrict__ out) {
    int node = blockIdx.x * 8 + (threadIdx.x >> 5);
    int c2 = threadIdx.x & 31;          // half2 index within a head
    if (node >= N_DST) return;
    int beg = g_off[node];
    int end = beg + g_deg[node];

    float d0 = 0.f, d1 = 0.f, d2 = 0.f, d3 = 0.f;
    for (int i = beg; i < end; i++) {
        float4 p = g_csr_ep[i];
        d0 += p.x; d1 += p.y; d2 += p.z; d3 += p.w;
    }
    float r0 = 0.25f / (d0 + EPS_DEN);
    float r1 = 0.25f / (d1 + EPS_DEN);
    float r2 = 0.25f / (d2 + EPS_DEN);
    float r3 = 0.25f / (d3 + EPS_DEN);

    float ax = 0.f, ay = 0.f;
    for (int i = beg; i < end; i++) {
        int s = g_csr_src[i];
        float4 p = g_csr_ep[i];
        const __half2* hr = reinterpret_cast<const __half2*>(&g_hsh[(size_t)s * HC]);
        float2 f0 = __half22float2(hr[c2]);
        float2 f1 = __half22float2(hr[32 + c2]);
        float2 f2 = __half22float2(hr[64 + c2]);
        float2 f3 = __half22float2(hr[96 + c2]);
        float w0 = p.x * r0, w1 = p.y * r1, w2 = p.z * r2, w3 = p.w * r3;
        ax += w0 * f0.x + w1 * f1.x + w2 * f2.x + w3 * f3.x;
        ay += w0 * f0.y + w1 * f1.y + w2 * f2.y + w3 * f3.y;
    }
    float2 res;
    res.x = ax + bias[c2 * 2];
    res.y = ay + bias[c2 * 2 + 1];
    *reinterpret_cast<float2*>(&out[(size_t)node * OUT_DIM + c2 * 2]) = res;
}

// ---------------- launch ----------------------------------------------------

extern "C" void kernel_launch(void* const* d_in, const int* in_sizes, int n_in,
                              void* d_out, int out_size) {
    const float* x_src   = (const float*)d_in[0];
    const float* x_dst   = (const float*)d_in[1];
    const int*   ei      = (const int*)d_in[2];   // [2, E] : src row then dst row
    const float* W_src   = (const float*)d_in[3];
    const float* W_dst   = (const float*)d_in[4];
    const float* att_src = (const float*)d_in[5];
    const float* att_dst = (const float*)d_in[6];
    const float* bias    = (const float*)d_in[7];
    float* out = (float*)d_out;

    const int* src = ei;
    const int* dst = ei + NEDGE;

    cudaFuncSetAttribute(k_gemm_mma, cudaFuncAttributeMaxDynamicSharedMemorySize, SM_TOTAL);

    k_zero_deg<<<(N_DST + 255) / 256, 256>>>();
    k_wt<<<64, 256>>>(W_src);
    k_vec<<<1, 512>>>(W_src, W_dst, att_src, att_dst);
    k_logits<<<(N_SRC + 255) / 256, 256>>>(x_src, x_dst);

    k_gemm_mma<<<M_TILES, 512, SM_TOTAL>>>(x_src);

    k_hist<<<(NEDGE + 255) / 256, 256>>>(dst);
    k_scan<<<1, 1024>>>();
    k_edge<<<(NEDGE + 255) / 256, 256>>>(src, dst);
    k_gather<<<(N_DST + 7) / 8, 256>>>(bias, out);
}

// round 6
// speedup vs baseline: 2.1299x; 1.3078x over previous
#include <cuda_runtime.h>
#include <cuda_fp16.h>
#include <cstdint>

#define N_SRC 50000
#define N_DST 50000
#define NEDGE 800000
#define IN_DIM 128
#define OUT_DIM 64
#define HEADS 4
#define HC 256              // HEADS * OUT_DIM
#define NEG_SLOPE 0.2f
#define EPS_DEN 1e-16f

#define M_TILES ((N_SRC + 127) / 128)   // 391

// ---------------- scratch (device globals; no allocation allowed) ----------
struct __align__(32) EdgeRec { float4 ep; int src; int pad[3]; };

__device__ __half g_hsh[(size_t)N_SRC * HC];      // 25.6 MB projected src feats (fp16)
__device__ __half g_wt[256 * 128];                // W^T fp16 [n][k] row-major (64KB)
__device__ float g_as[N_SRC * HEADS];             // per-node src logits
__device__ float g_ad[N_DST * HEADS];             // per-node dst logits
__device__ float g_vs[IN_DIM * HEADS];            // W_src @ att_src (folded)
__device__ float g_vd[IN_DIM * HEADS];            // W_dst @ att_dst (folded)
__device__ int   g_deg[N_DST];                    // in-degree histogram
__device__ int   g_off[N_DST];                    // CSR row offsets
__device__ int   g_cur[N_DST];                    // CSR write cursors
__device__ EdgeRec g_csr[NEDGE];                  // CSR records (25.6 MB)

// ---------------- mma/ldmatrix helpers (family-portable, sm_80+) -----------
__device__ __forceinline__ void ldsm_x4(uint32_t& r0, uint32_t& r1, uint32_t& r2,
                                        uint32_t& r3, uint32_t addr) {
    asm volatile("ldmatrix.sync.aligned.m8n8.x4.shared.b16 {%0,%1,%2,%3}, [%4];"
                 : "=r"(r0), "=r"(r1), "=r"(r2), "=r"(r3) : "r"(addr));
}
__device__ __forceinline__ void mma16816(float& d0, float& d1, float& d2, float& d3,
                                         uint32_t a0, uint32_t a1, uint32_t a2, uint32_t a3,
                                         uint32_t b0, uint32_t b1) {
    asm volatile(
        "mma.sync.aligned.m16n8k16.row.col.f32.f16.f16.f32 "
        "{%0,%1,%2,%3}, {%4,%5,%6,%7}, {%8,%9}, {%0,%1,%2,%3};"
        : "+f"(d0), "+f"(d1), "+f"(d2), "+f"(d3)
        : "r"(a0), "r"(a1), "r"(a2), "r"(a3), "r"(b0), "r"(b1));
}

// ---------------- kernels ---------------------------------------------------

__global__ void k_zero_deg() {
    int i = blockIdx.x * blockDim.x + threadIdx.x;
    if (i < N_DST) g_deg[i] = 0;
}

// transpose + fp16-convert W_src -> g_wt [n=256][k=128] row-major
__global__ void k_wt(const float* __restrict__ W) {
    int t = blockIdx.x * blockDim.x + threadIdx.x;   // 0..16383 (one half2 each)
    int n = t & 255;
    int k2 = t >> 8;                                 // half2 index 0..63
    float w0 = W[(size_t)(2 * k2) * HC + n];
    float w1 = W[(size_t)(2 * k2 + 1) * HC + n];
    __half2 h = __floats2half2_rn(w0, w1);
    *reinterpret_cast<__half2*>(&g_wt[n * 128 + 2 * k2]) = h;
}

// v_s[k,h] = sum_c W_src[k, h*64+c] * att_src[h,c]   (and same for dst)
__global__ void k_vec(const float* __restrict__ Ws, const float* __restrict__ Wd,
                      const float* __restrict__ att_s, const float* __restrict__ att_d) {
    int t = threadIdx.x;            // 512 threads, 1 block
    int k = t >> 2;
    int h = t & 3;
    float s = 0.0f, d = 0.0f;
#pragma unroll 8
    for (int c = 0; c < OUT_DIM; c++) {
        s += Ws[(size_t)k * HC + h * OUT_DIM + c] * att_s[h * OUT_DIM + c];
        d += Wd[(size_t)k * HC + h * OUT_DIM + c] * att_d[h * OUT_DIM + c];
    }
    g_vs[k * HEADS + h] = s;
    g_vd[k * HEADS + h] = d;
}

// a_s = x_src @ v_s ; a_d = x_dst @ v_d.  4 threads per node, coalesced.
__global__ void k_logits(const float* __restrict__ xs, const float* __restrict__ xd) {
    __shared__ float vs[IN_DIM * HEADS];
    __shared__ float vd[IN_DIM * HEADS];
    for (int i = threadIdx.x; i < IN_DIM * HEADS; i += blockDim.x) {
        vs[i] = g_vs[i];
        vd[i] = g_vd[i];
    }
    __syncthreads();
    int idx = blockIdx.x * blockDim.x + threadIdx.x;
    int n = idx >> 2;
    int g = idx & 3;
    if (n >= N_SRC) return;

    float ss[4] = {0.f, 0.f, 0.f, 0.f};
    float dd[4] = {0.f, 0.f, 0.f, 0.f};
    const float4* xr  = reinterpret_cast<const float4*>(xs + (size_t)n * IN_DIM);
    const float4* xdr = reinterpret_cast<const float4*>(xd + (size_t)n * IN_DIM);
#pragma unroll
    for (int k4 = 0; k4 < 8; k4++) {
        int f4 = k4 * 4 + g;             // float4 index; lanes g=0..3 contiguous 64B
        float4 a = xr[f4];
        float4 b = xdr[f4];
        int base = f4 * 4 * HEADS;
#pragma unroll
        for (int h = 0; h < HEADS; h++) {
            ss[h] += a.x * vs[base + 0 * HEADS + h] + a.y * vs[base + 1 * HEADS + h]
                   + a.z * vs[base + 2 * HEADS + h] + a.w * vs[base + 3 * HEADS + h];
            dd[h] += b.x * vd[base + 0 * HEADS + h] + b.y * vd[base + 1 * HEADS + h]
                   + b.z * vd[base + 2 * HEADS + h] + b.w * vd[base + 3 * HEADS + h];
        }
    }
#pragma unroll
    for (int off = 1; off < 4; off <<= 1) {
#pragma unroll
        for (int h = 0; h < HEADS; h++) {
            ss[h] += __shfl_xor_sync(0xffffffffu, ss[h], off);
            dd[h] += __shfl_xor_sync(0xffffffffu, dd[h], off);
        }
    }
    if (g == 0) {
        *reinterpret_cast<float4*>(&g_as[n * HEADS]) = make_float4(ss[0], ss[1], ss[2], ss[3]);
        *reinterpret_cast<float4*>(&g_ad[n * HEADS]) = make_float4(dd[0], dd[1], dd[2], dd[3]);
    }
}

// hs = x_src @ W_src via HMMA (fp16 in, f32 accum) -> g_hsh [N_SRC, 256] fp16
#define AS_STRIDE 272
#define AS_BYTES (128 * AS_STRIDE)       // 34816
#define BS_BYTES (256 * AS_STRIDE)       // 69632
#define SM_TOTAL (AS_BYTES + BS_BYTES)   // 104448

__global__ void __launch_bounds__(512) k_gemm_mma(const float* __restrict__ A) {
    extern __shared__ char smem[];
    char* As = smem;
    char* Bs = smem + AS_BYTES;
    int tid = threadIdx.x;
    int lane = tid & 31;
    int warp = tid >> 5;
    int rowBase = blockIdx.x * 128;

    for (int i = tid; i < 128 * 32; i += 512) {
        int r = i >> 5;
        int c4 = i & 31;
        int grow = rowBase + r;
        float4 v = make_float4(0.f, 0.f, 0.f, 0.f);
        if (grow < N_SRC)
            v = *reinterpret_cast<const float4*>(&A[(size_t)grow * IN_DIM + c4 * 4]);
        __half2 h0 = __floats2half2_rn(v.x, v.y);
        __half2 h1 = __floats2half2_rn(v.z, v.w);
        uint2 st;
        st.x = *reinterpret_cast<uint32_t*>(&h0);
        st.y = *reinterpret_cast<uint32_t*>(&h1);
        *reinterpret_cast<uint2*>(As + r * AS_STRIDE + c4 * 8) = st;
    }
    for (int i = tid; i < 256 * 16; i += 512) {
        int r = i >> 4;
        int c = i & 15;
        uint4 v = *reinterpret_cast<const uint4*>(&g_wt[r * 128 + c * 8]);
        *reinterpret_cast<uint4*>(Bs + r * AS_STRIDE + c * 16) = v;
    }
    __syncthreads();

    int wm = warp >> 2;
    int wn = warp & 3;
    int m0 = wm * 32;
    int n0 = wn * 64;

    float acc[2][8][4];
#pragma unroll
    for (int mi = 0; mi < 2; mi++)
#pragma unroll
        for (int ni = 0; ni < 8; ni++)
#pragma unroll
            for (int q = 0; q < 4; q++) acc[mi][ni][q] = 0.f;

    uint32_t asb = (uint32_t)__cvta_generic_to_shared(As);
    uint32_t bsb = (uint32_t)__cvta_generic_to_shared(Bs);

#pragma unroll
    for (int ks = 0; ks < 8; ks++) {
        int kb = ks * 32;
        uint32_t a[2][4];
#pragma unroll
        for (int mi = 0; mi < 2; mi++) {
            uint32_t addr = asb + (m0 + mi * 16 + (lane & 15)) * AS_STRIDE
                          + kb + (lane >> 4) * 16;
            ldsm_x4(a[mi][0], a[mi][1], a[mi][2], a[mi][3], addr);
        }
        uint32_t b[8][2];
#pragma unroll
        for (int np = 0; np < 4; np++) {
            int q = lane >> 3;
            int row = n0 + np * 16 + (q >> 1) * 8 + (lane & 7);
            uint32_t addr = bsb + row * AS_STRIDE + kb + (q & 1) * 16;
            ldsm_x4(b[np * 2][0], b[np * 2][1], b[np * 2 + 1][0], b[np * 2 + 1][1], addr);
        }
#pragma unroll
        for (int mi = 0; mi < 2; mi++)
#pragma unroll
            for (int ni = 0; ni < 8; ni++)
                mma16816(acc[mi][ni][0], acc[mi][ni][1], acc[mi][ni][2], acc[mi][ni][3],
                         a[mi][0], a[mi][1], a[mi][2], a[mi][3],
                         b[ni][0], b[ni][1]);
    }

#pragma unroll
    for (int mi = 0; mi < 2; mi++) {
        int r0 = rowBase + m0 + mi * 16 + (lane >> 2);
        int r1 = r0 + 8;
#pragma unroll
        for (int ni = 0; ni < 8; ni++) {
            int col = n0 + ni * 8 + 2 * (lane & 3);
            if (r0 < N_SRC) {
                __half2 h = __floats2half2_rn(acc[mi][ni][0], acc[mi][ni][1]);
                *reinterpret_cast<__half2*>(&g_hsh[(size_t)r0 * HC + col]) = h;
            }
            if (r1 < N_SRC) {
                __half2 h = __floats2half2_rn(acc[mi][ni][2], acc[mi][ni][3]);
                *reinterpret_cast<__half2*>(&g_hsh[(size_t)r1 * HC + col]) = h;
            }
        }
    }
}

// in-degree histogram
__global__ void k_hist(const int* __restrict__ dst) {
    int e = blockIdx.x * blockDim.x + threadIdx.x;
    if (e < NEDGE) atomicAdd(&g_deg[dst[e]], 1);
}

// exclusive scan of g_deg -> g_off, g_cur.  Single block of 1024 threads.
__global__ void __launch_bounds__(1024) k_scan() {
    __shared__ int sums[1024];
    const int CH = (N_DST + 1023) / 1024;   // 49
    int t = threadIdx.x;
    int beg = t * CH;
    int end = beg + CH; if (end > N_DST) end = N_DST;
    int s = 0;
    for (int i = beg; i < end; i++) s += g_deg[i];
    sums[t] = s;
    __syncthreads();
    for (int off = 1; off < 1024; off <<= 1) {
        int v = (t >= off) ? sums[t - off] : 0;
        __syncthreads();
        sums[t] += v;
        __syncthreads();
    }
    int run = (t == 0) ? 0 : sums[t - 1];
    for (int i = beg; i < end; i++) {
        g_off[i] = run;
        g_cur[i] = run;
        run += g_deg[i];
    }
}

__device__ __forceinline__ float lrelu(float v) {
    return v > 0.0f ? v : NEG_SLOPE * v;
}

// per-edge exp(leaky(a_s[src]+a_d[dst])), bucketed into CSR order
__global__ void k_edge(const int* __restrict__ src, const int* __restrict__ dst) {
    int e = blockIdx.x * blockDim.x + threadIdx.x;
    if (e >= NEDGE) return;
    int s = src[e], d = dst[e];
    float4 as4 = *reinterpret_cast<const float4*>(&g_as[s * HEADS]);
    float4 ad4 = *reinterpret_cast<const float4*>(&g_ad[d * HEADS]);
    float4 pp;
    pp.x = expf(lrelu(as4.x + ad4.x));
    pp.y = expf(lrelu(as4.y + ad4.y));
    pp.z = expf(lrelu(as4.z + ad4.z));
    pp.w = expf(lrelu(as4.w + ad4.w));
    int pos = atomicAdd(&g_cur[d], 1);
    g_csr[pos].ep = pp;
    g_csr[pos].src = s;
}

// gather: 1 warp per dst node, each thread owns 2 channels.
__global__ void __launch_bounds__(256) k_gather(const float* __restrict__ bias,
                                                float* __restrict__ out) {
    int node = blockIdx.x * 8 + (threadIdx.x >> 5);
    int c2 = threadIdx.x & 31;          // half2 index within a head
    if (node >= N_DST) return;
    int beg = g_off[node];
    int end = beg + g_deg[node];

    float d0 = 0.f, d1 = 0.f, d2 = 0.f, d3 = 0.f;
    for (int i = beg; i < end; i++) {
        float4 p = g_csr[i].ep;
        d0 += p.x; d1 += p.y; d2 += p.z; d3 += p.w;
    }
    float r0 = 0.25f / (d0 + EPS_DEN);
    float r1 = 0.25f / (d1 + EPS_DEN);
    float r2 = 0.25f / (d2 + EPS_DEN);
    float r3 = 0.25f / (d3 + EPS_DEN);

    float ax = 0.f, ay = 0.f;
    for (int i = beg; i < end; i++) {
        float4 p = g_csr[i].ep;
        int s = g_csr[i].src;
        const __half2* hr = reinterpret_cast<const __half2*>(&g_hsh[(size_t)s * HC]);
        float2 f0 = __half22float2(hr[c2]);
        float2 f1 = __half22float2(hr[32 + c2]);
        float2 f2 = __half22float2(hr[64 + c2]);
        float2 f3 = __half22float2(hr[96 + c2]);
        float w0 = p.x * r0, w1 = p.y * r1, w2 = p.z * r2, w3 = p.w * r3;
        ax += w0 * f0.x + w1 * f1.x + w2 * f2.x + w3 * f3.x;
        ay += w0 * f0.y + w1 * f1.y + w2 * f2.y + w3 * f3.y;
    }
    float2 res;
    res.x = ax + bias[c2 * 2];
    res.y = ay + bias[c2 * 2 + 1];
    *reinterpret_cast<float2*>(&out[(size_t)node * OUT_DIM + c2 * 2]) = res;
}

// ---------------- streams / events (created at load, reused) ----------------
static cudaStream_t s_aux1, s_aux2;
static cudaEvent_t ev_root, ev_logits, ev_gemm;
static int s_init = [] {
    cudaStreamCreateWithFlags(&s_aux1, cudaStreamNonBlocking);
    cudaStreamCreateWithFlags(&s_aux2, cudaStreamNonBlocking);
    cudaEventCreateWithFlags(&ev_root, cudaEventDisableTiming);
    cudaEventCreateWithFlags(&ev_logits, cudaEventDisableTiming);
    cudaEventCreateWithFlags(&ev_gemm, cudaEventDisableTiming);
    return 0;
}();

// ---------------- launch ----------------------------------------------------

extern "C" void kernel_launch(void* const* d_in, const int* in_sizes, int n_in,
                              void* d_out, int out_size) {
    const float* x_src   = (const float*)d_in[0];
    const float* x_dst   = (const float*)d_in[1];
    const int*   ei      = (const int*)d_in[2];   // [2, E] : src row then dst row
    const float* W_src   = (const float*)d_in[3];
    const float* W_dst   = (const float*)d_in[4];
    const float* att_src = (const float*)d_in[5];
    const float* att_dst = (const float*)d_in[6];
    const float* bias    = (const float*)d_in[7];
    float* out = (float*)d_out;

    const int* src = ei;
    const int* dst = ei + NEDGE;

    cudaFuncSetAttribute(k_gemm_mma, cudaFuncAttributeMaxDynamicSharedMemorySize, SM_TOTAL);

    cudaStream_t s0 = 0;   // capture-origin (default) stream

    // fork
    cudaEventRecord(ev_root, s0);
    cudaStreamWaitEvent(s_aux1, ev_root, 0);
    cudaStreamWaitEvent(s_aux2, ev_root, 0);

    // aux1: logits chain
    k_vec<<<1, 512, 0, s_aux1>>>(W_src, W_dst, att_src, att_dst);
    k_logits<<<(N_SRC * 4 + 255) / 256, 256, 0, s_aux1>>>(x_src, x_dst);
    cudaEventRecord(ev_logits, s_aux1);

    // aux2: gemm chain
    k_wt<<<64, 256, 0, s_aux2>>>(W_src);
    k_gemm_mma<<<M_TILES, 512, SM_TOTAL, s_aux2>>>(x_src);
    cudaEventRecord(ev_gemm, s_aux2);

    // origin: hist chain, then joins
    k_zero_deg<<<(N_DST + 255) / 256, 256, 0, s0>>>();
    k_hist<<<(NEDGE + 255) / 256, 256, 0, s0>>>(dst);
    k_scan<<<1, 1024, 0, s0>>>();
    cudaStreamWaitEvent(s0, ev_logits, 0);
    k_edge<<<(NEDGE + 255) / 256, 256, 0, s0>>>(src, dst);
    cudaStreamWaitEvent(s0, ev_gemm, 0);
    k_gather<<<(N_DST + 7) / 8, 256, 0, s0>>>(bias, out);
}